// round 12
// baseline (speedup 1.0000x reference)
#include <cuda_runtime.h>
#include <cuda_bf16.h>
#include <math.h>
#include <stdint.h>

#define N_NODES 100000
#define N_EDGES 1600000
#define DIM 128           // in dim == out dim (8 heads * 16)
#define N_HEADS 8
#define LEAKY 0.2f
#define EPS 1e-16f

#define SA_STRIDE 132
#define SB_STRIDE 133
#define SCAN_THREADS 1024
#define NBLK_SCAN 98      // ceil(100000/1024)

// ---------------- scratch (device globals; no allocation allowed) ----------------
__device__ float g_h[(size_t)N_NODES * DIM];            // x @ W_lin (tf32 mma)
__device__ float g_alpha_l[N_NODES * N_HEADS];
__device__ float g_alpha_r[N_NODES * N_HEADS];
__device__ int   g_deg[N_NODES];
__device__ int   g_row[N_NODES + 1];
__device__ int   g_cursor[N_NODES];
__device__ int   g_csr_src[N_EDGES];
__device__ int   g_partial[NBLK_SCAN];

// ---------------- streams/events: created pre-main (static ctor) ----------------
static cudaStream_t s_side = 0;
static cudaEvent_t  ev_fork = 0, ev_join = 0;
static bool s_ok = false;
namespace {
struct StreamInit {
    StreamInit() {
        s_ok = (cudaStreamCreateWithFlags(&s_side, cudaStreamNonBlocking) == cudaSuccess)
            && (cudaEventCreateWithFlags(&ev_fork, cudaEventDisableTiming) == cudaSuccess)
            && (cudaEventCreateWithFlags(&ev_join, cudaEventDisableTiming) == cudaSuccess);
    }
} s_stream_init;
}

// -------- hot-load helpers: createpolicy + cache_hint (legal on sm_100 for any
// width, unlike the bare .L2::evict_last qualifier which needs 256-bit loads) ----
__device__ __forceinline__ uint64_t mk_evict_last_policy() {
    uint64_t pol;
    asm volatile("createpolicy.fractional.L2::evict_last.b64 %0, 1.0;" : "=l"(pol));
    return pol;
}
__device__ __forceinline__ float4 ldg_keep_f4(const float* p, uint64_t pol) {
    float4 v;
    asm volatile("ld.global.nc.L2::cache_hint.v4.f32 {%0,%1,%2,%3}, [%4], %5;"
                 : "=f"(v.x), "=f"(v.y), "=f"(v.z), "=f"(v.w) : "l"(p), "l"(pol));
    return v;
}
__device__ __forceinline__ float ldg_keep_f(const float* p, uint64_t pol) {
    float v;
    asm volatile("ld.global.nc.L2::cache_hint.f32 %0, [%1], %2;"
                 : "=f"(v) : "l"(p), "l"(pol));
    return v;
}

// ============================ CSR build =====================================
__global__ void zero_deg_kernel() {
    int gid = blockIdx.x * blockDim.x + threadIdx.x;
    if (gid < N_NODES) g_deg[gid] = 0;
}

__global__ void hist_kernel(const int* __restrict__ eidx) {
    int gid = blockIdx.x * blockDim.x + threadIdx.x;
    if (gid < N_EDGES / 4) {
        int4 d4 = __ldcs(reinterpret_cast<const int4*>(eidx + N_EDGES) + gid);
        atomicAdd(&g_deg[d4.x], 1);
        atomicAdd(&g_deg[d4.y], 1);
        atomicAdd(&g_deg[d4.z], 1);
        atomicAdd(&g_deg[d4.w], 1);
    }
}

// block-local exclusive scan of g_deg -> g_row (pre-offset), block INCLUSIVE sums -> g_partial
__global__ void scan_local_kernel() {
    __shared__ int warp_sums[32];
    int gid = blockIdx.x * SCAN_THREADS + threadIdx.x;
    int v = (gid < N_NODES) ? g_deg[gid] : 0;
    int x = v;
    int lane = threadIdx.x & 31;
    #pragma unroll
    for (int o = 1; o < 32; o <<= 1) {
        int y = __shfl_up_sync(0xffffffffu, x, o);
        if (lane >= o) x += y;
    }
    if (lane == 31) warp_sums[threadIdx.x >> 5] = x;
    __syncthreads();
    if (threadIdx.x < 32) {
        int w = warp_sums[threadIdx.x];
        #pragma unroll
        for (int o = 1; o < 32; o <<= 1) {
            int y = __shfl_up_sync(0xffffffffu, w, o);
            if (threadIdx.x >= o) w += y;
        }
        warp_sums[threadIdx.x] = w;
    }
    __syncthreads();
    int base = (threadIdx.x >= 32) ? warp_sums[(threadIdx.x >> 5) - 1] : 0;
    int incl = x + base;
    if (gid < N_NODES) g_row[gid] = incl - v;      // exclusive (block-local)
    if (threadIdx.x == SCAN_THREADS - 1) g_partial[blockIdx.x] = incl;
}

// add block offsets; each block computes its own prefix of the 98 partials inline
__global__ void add_offsets_kernel() {
    __shared__ int s_base;
    if (threadIdx.x < 32) {
        int s = 0;
        for (int i = threadIdx.x; i < blockIdx.x && i < NBLK_SCAN; i += 32)
            s += g_partial[i];
        #pragma unroll
        for (int o = 16; o > 0; o >>= 1)
            s += __shfl_xor_sync(0xffffffffu, s, o);
        if (threadIdx.x == 0) s_base = s;
    }
    __syncthreads();
    int gid = blockIdx.x * SCAN_THREADS + threadIdx.x;
    if (gid < N_NODES) {
        int r = g_row[gid] + s_base;
        g_row[gid] = r;
        g_cursor[gid] = r;
    }
    if (gid == 0) g_row[N_NODES] = N_EDGES;
}

__global__ void place_kernel(const int* __restrict__ eidx) {
    int gid = blockIdx.x * blockDim.x + threadIdx.x;
    if (gid < N_EDGES / 4) {
        int4 s4 = __ldcs(reinterpret_cast<const int4*>(eidx) + gid);
        int4 d4 = __ldcs(reinterpret_cast<const int4*>(eidx + N_EDGES) + gid);
        int p0 = atomicAdd(&g_cursor[d4.x], 1);
        int p1 = atomicAdd(&g_cursor[d4.y], 1);
        int p2 = atomicAdd(&g_cursor[d4.z], 1);
        int p3 = atomicAdd(&g_cursor[d4.w], 1);
        g_csr_src[p0] = s4.x;
        g_csr_src[p1] = s4.y;
        g_csr_src[p2] = s4.z;
        g_csr_src[p3] = s4.w;
    }
}

// ======================= tf32 tensor-core dual GEMM =========================
// Single pass over x: one block computes BOTH W_lin and W_res outputs from one
// sA load (x read once from DRAM; streamed with .cs to spare L2 for the gather).
__device__ __forceinline__ uint32_t f2tf32(float f) {
    uint32_t r;
    asm("cvt.rna.tf32.f32 %0, %1;" : "=r"(r) : "f"(f));
    return r;
}

__global__ void __launch_bounds__(256, 1)
gemm_tf32_kernel(const float* __restrict__ x,
                 const float* __restrict__ Wlin,
                 const float* __restrict__ Wres,
                 float* __restrict__ out_res) {
    extern __shared__ uint32_t smem_u[];
    uint32_t* sA = smem_u;                       // [128][SA_STRIDE]
    uint32_t* sB = smem_u + 128 * SA_STRIDE;     // [128][SB_STRIDE] (n,k)

    const int tid = threadIdx.x;
    const int row0 = blockIdx.x * 128;

    for (int i = tid; i < 128 * 32; i += 256) {
        int r = i >> 5, c4 = i & 31;
        float4 v = make_float4(0.f, 0.f, 0.f, 0.f);
        if (row0 + r < N_NODES)
            v = __ldcs(reinterpret_cast<const float4*>(x + (size_t)(row0 + r) * DIM + c4 * 4));
        uint4 u;
        u.x = f2tf32(v.x); u.y = f2tf32(v.y); u.z = f2tf32(v.z); u.w = f2tf32(v.w);
        *reinterpret_cast<uint4*>(sA + r * SA_STRIDE + c4 * 4) = u;
    }

    const int warp = tid >> 5, lane = tid & 31;
    const int wm = warp >> 1, wn = warp & 1;
    const int g = lane >> 2, tig = lane & 3;

    for (int wsel = 0; wsel < 2; wsel++) {
        const float* W = wsel ? Wres : Wlin;
        for (int i = tid; i < 128 * 128; i += 256) {
            int k = i >> 7, n = i & 127;
            sB[n * SB_STRIDE + k] = f2tf32(W[k * DIM + n]);
        }
        __syncthreads();

        float acc[2][8][4];
        #pragma unroll
        for (int i = 0; i < 2; i++)
            #pragma unroll
            for (int j = 0; j < 8; j++)
                #pragma unroll
                for (int c = 0; c < 4; c++) acc[i][j][c] = 0.f;

        #pragma unroll
        for (int ks = 0; ks < 16; ks++) {
            const int k0 = ks * 8;
            uint32_t bf0[8], bf1[8];
            #pragma unroll
            for (int j = 0; j < 8; j++) {
                int n = wn * 64 + j * 8 + g;
                bf0[j] = sB[n * SB_STRIDE + k0 + tig];
                bf1[j] = sB[n * SB_STRIDE + k0 + 4 + tig];
            }
            #pragma unroll
            for (int i = 0; i < 2; i++) {
                int m = wm * 32 + i * 16;
                uint32_t a0 = sA[(m + g) * SA_STRIDE + k0 + tig];
                uint32_t a1 = sA[(m + 8 + g) * SA_STRIDE + k0 + tig];
                uint32_t a2 = sA[(m + g) * SA_STRIDE + k0 + 4 + tig];
                uint32_t a3 = sA[(m + 8 + g) * SA_STRIDE + k0 + 4 + tig];
                #pragma unroll
                for (int j = 0; j < 8; j++) {
                    asm volatile(
                        "mma.sync.aligned.m16n8k8.row.col.f32.tf32.tf32.f32 "
                        "{%0,%1,%2,%3}, {%4,%5,%6,%7}, {%8,%9}, {%0,%1,%2,%3};"
                        : "+f"(acc[i][j][0]), "+f"(acc[i][j][1]),
                          "+f"(acc[i][j][2]), "+f"(acc[i][j][3])
                        : "r"(a0), "r"(a1), "r"(a2), "r"(a3),
                          "r"(bf0[j]), "r"(bf1[j]));
                }
            }
        }

        #pragma unroll
        for (int i = 0; i < 2; i++) {
            #pragma unroll
            for (int j = 0; j < 8; j++) {
                int col = wn * 64 + j * 8 + tig * 2;
                int r0 = row0 + wm * 32 + i * 16 + g;
                int r1 = r0 + 8;
                if (wsel == 0) {
                    // g_h stays default policy (hot: read by alpha + aggregate)
                    if (r0 < N_NODES)
                        *reinterpret_cast<float2*>(&g_h[(size_t)r0 * DIM + col]) =
                            make_float2(acc[i][j][0], acc[i][j][1]);
                    if (r1 < N_NODES)
                        *reinterpret_cast<float2*>(&g_h[(size_t)r1 * DIM + col]) =
                            make_float2(acc[i][j][2], acc[i][j][3]);
                } else {
                    // residual: single-use until aggregate -> streaming store
                    if (r0 < N_NODES)
                        __stcs(reinterpret_cast<float2*>(out_res + (size_t)r0 * DIM + col),
                               make_float2(acc[i][j][0], acc[i][j][1]));
                    if (r1 < N_NODES)
                        __stcs(reinterpret_cast<float2*>(out_res + (size_t)r1 * DIM + col),
                               make_float2(acc[i][j][2], acc[i][j][3]));
                }
            }
        }
        __syncthreads();
    }
}

// ======================= per-node attention logits ==========================
__global__ void alpha_kernel(const float* __restrict__ att_l,
                             const float* __restrict__ att_r) {
    __shared__ float sal[DIM], sar[DIM];
    if (threadIdx.x < DIM) {
        sal[threadIdx.x] = att_l[threadIdx.x];
        sar[threadIdx.x] = att_r[threadIdx.x];
    }
    __syncthreads();
    int gid = blockIdx.x * blockDim.x + threadIdx.x;
    if (gid >= N_NODES * N_HEADS) return;
    int n = gid >> 3;
    int hh = gid & 7;
    const float* hp = &g_h[(size_t)n * DIM + hh * 16];
    float al = 0.f, ar = 0.f;
    #pragma unroll
    for (int c = 0; c < 16; c++) {
        float hv = hp[c];
        al = fmaf(hv, sal[hh * 16 + c], al);
        ar = fmaf(hv, sar[hh * 16 + c], ar);
    }
    g_alpha_l[gid] = al;
    g_alpha_r[gid] = ar;
}

// ============ single-pass fused softmax + gather + ELU + residual ===========
// one warp per destination node. The CSR row is contiguous, so ONE coalesced
// load (lane < deg) brings up to 32 src indices into registers; the gather loop
// gets each src via shfl (ALU, no scoreboard) -- the csr->gather dependent L2
// round trip per batch is eliminated. Hot arrays get evict_last cache policy.
__global__ void __launch_bounds__(256, 4)
aggregate_kernel(float* __restrict__ out) {
    int wid_g = (blockIdx.x * blockDim.x + threadIdx.x) >> 5;
    int lane = threadIdx.x & 31;
    if (wid_g >= N_NODES) return;
    const int dst = wid_g;
    const uint64_t pol = mk_evict_last_policy();
    const int beg = __ldg(&g_row[dst]);
    const int end = __ldg(&g_row[dst + 1]);
    const int deg = end - beg;
    const int head = lane >> 2;                    // head owning this float4

    const float ar = ldg_keep_f(&g_alpha_r[dst * N_HEADS + head], pol);

    // one coalesced index load: lane L holds src of edge beg+L (covers deg<=32)
    int mySrc = (lane < deg) ? __ldg(&g_csr_src[beg + lane]) : 0;

    float4 acc0 = make_float4(0.f, 0.f, 0.f, 0.f);
    float4 acc1 = make_float4(0.f, 0.f, 0.f, 0.f);
    float hsum = 0.f;                              // identical across 4 lanes of group

    const int nfast = (deg < 32) ? deg : 32;
    int i = 0;
    for (; i + 3 < nfast; i += 4) {
        int s0 = __shfl_sync(0xffffffffu, mySrc, i + 0);
        int s1 = __shfl_sync(0xffffffffu, mySrc, i + 1);
        int s2 = __shfl_sync(0xffffffffu, mySrc, i + 2);
        int s3 = __shfl_sync(0xffffffffu, mySrc, i + 3);
        float a0 = ldg_keep_f(&g_alpha_l[s0 * N_HEADS + head], pol) + ar;
        float a1 = ldg_keep_f(&g_alpha_l[s1 * N_HEADS + head], pol) + ar;
        float a2 = ldg_keep_f(&g_alpha_l[s2 * N_HEADS + head], pol) + ar;
        float a3 = ldg_keep_f(&g_alpha_l[s3 * N_HEADS + head], pol) + ar;
        a0 = (a0 > 0.f) ? a0 : LEAKY * a0;
        a1 = (a1 > 0.f) ? a1 : LEAKY * a1;
        a2 = (a2 > 0.f) ? a2 : LEAKY * a2;
        a3 = (a3 > 0.f) ? a3 : LEAKY * a3;
        float x0 = __expf(a0), x1 = __expf(a1), x2 = __expf(a2), x3 = __expf(a3);
        float4 h0 = ldg_keep_f4(&g_h[(size_t)s0 * DIM + lane * 4], pol);
        float4 h1 = ldg_keep_f4(&g_h[(size_t)s1 * DIM + lane * 4], pol);
        float4 h2 = ldg_keep_f4(&g_h[(size_t)s2 * DIM + lane * 4], pol);
        float4 h3 = ldg_keep_f4(&g_h[(size_t)s3 * DIM + lane * 4], pol);
        hsum += (x0 + x1) + (x2 + x3);
        acc0.x = fmaf(h0.x, x0, acc0.x); acc0.y = fmaf(h0.y, x0, acc0.y);
        acc0.z = fmaf(h0.z, x0, acc0.z); acc0.w = fmaf(h0.w, x0, acc0.w);
        acc1.x = fmaf(h1.x, x1, acc1.x); acc1.y = fmaf(h1.y, x1, acc1.y);
        acc1.z = fmaf(h1.z, x1, acc1.z); acc1.w = fmaf(h1.w, x1, acc1.w);
        acc0.x = fmaf(h2.x, x2, acc0.x); acc0.y = fmaf(h2.y, x2, acc0.y);
        acc0.z = fmaf(h2.z, x2, acc0.z); acc0.w = fmaf(h2.w, x2, acc0.w);
        acc1.x = fmaf(h3.x, x3, acc1.x); acc1.y = fmaf(h3.y, x3, acc1.y);
        acc1.z = fmaf(h3.z, x3, acc1.z); acc1.w = fmaf(h3.w, x3, acc1.w);
    }
    for (; i < nfast; i++) {
        int s = __shfl_sync(0xffffffffu, mySrc, i);
        float a = ldg_keep_f(&g_alpha_l[s * N_HEADS + head], pol) + ar;
        a = (a > 0.f) ? a : LEAKY * a;
        float ex = __expf(a);
        float4 hv = ldg_keep_f4(&g_h[(size_t)s * DIM + lane * 4], pol);
        hsum += ex;
        acc0.x = fmaf(hv.x, ex, acc0.x); acc0.y = fmaf(hv.y, ex, acc0.y);
        acc0.z = fmaf(hv.z, ex, acc0.z); acc0.w = fmaf(hv.w, ex, acc0.w);
    }
    // rare fallback: deg > 32 (Poisson(16) tail)
    for (int e = beg + 32; e < end; e++) {
        int s = __ldg(&g_csr_src[e]);
        float a = ldg_keep_f(&g_alpha_l[s * N_HEADS + head], pol) + ar;
        a = (a > 0.f) ? a : LEAKY * a;
        float ex = __expf(a);
        float4 hv = ldg_keep_f4(&g_h[(size_t)s * DIM + lane * 4], pol);
        hsum += ex;
        acc0.x = fmaf(hv.x, ex, acc0.x); acc0.y = fmaf(hv.y, ex, acc0.y);
        acc0.z = fmaf(hv.z, ex, acc0.z); acc0.w = fmaf(hv.w, ex, acc0.w);
    }

    const float inv = 1.f / (hsum + EPS);
    float4 acc;
    acc.x = (acc0.x + acc1.x) * inv;
    acc.y = (acc0.y + acc1.y) * inv;
    acc.z = (acc0.z + acc1.z) * inv;
    acc.w = (acc0.w + acc1.w) * inv;

    float* op = out + (size_t)dst * DIM + lane * 4;
    float4 r = __ldcs(reinterpret_cast<const float4*>(op));  // residual, single use
    float4 o;
    o.x = ((acc.x > 0.f) ? acc.x : expm1f(acc.x)) + r.x;
    o.y = ((acc.y > 0.f) ? acc.y : expm1f(acc.y)) + r.y;
    o.z = ((acc.z > 0.f) ? acc.z : expm1f(acc.z)) + r.z;
    o.w = ((acc.w > 0.f) ? acc.w : expm1f(acc.w)) + r.w;
    __stcs(reinterpret_cast<float4*>(op), o);
}

// ================================ launch ====================================
extern "C" void kernel_launch(void* const* d_in, const int* in_sizes, int n_in,
                              void* d_out, int out_size) {
    const float* x     = (const float*)d_in[0];
    const int*   eidx  = (const int*)d_in[1];
    const float* Wlin  = (const float*)d_in[2];
    const float* att_l = (const float*)d_in[3];
    const float* att_r = (const float*)d_in[4];
    const float* Wres  = (const float*)d_in[5];
    float* out = (float*)d_out;

    static bool attr_set = false;
    const size_t smem_bytes = (128 * SA_STRIDE + 128 * SB_STRIDE) * sizeof(uint32_t);
    if (!attr_set) {
        cudaFuncSetAttribute(gemm_tf32_kernel,
                             cudaFuncAttributeMaxDynamicSharedMemorySize, (int)smem_bytes);
        attr_set = true;
    }

    const bool fork = s_ok;
    cudaStream_t sg = fork ? s_side : (cudaStream_t)0;

    if (fork) {
        cudaEventRecord(ev_fork, 0);
        cudaStreamWaitEvent(sg, ev_fork, 0);
    }

    // side stream: dual GEMM (g_h = x@W_lin AND d_out = x@W_res, one x pass) + logits
    gemm_tf32_kernel<<<(N_NODES + 127) / 128, 256, smem_bytes, sg>>>(x, Wlin, Wres, out);
    alpha_kernel<<<(N_NODES * N_HEADS + 255) / 256, 256, 0, sg>>>(att_l, att_r);

    // main stream: CSR build (by destination)
    zero_deg_kernel<<<(N_NODES + 255) / 256, 256>>>();
    hist_kernel<<<(N_EDGES / 4 + 255) / 256, 256>>>(eidx);
    scan_local_kernel<<<NBLK_SCAN, SCAN_THREADS>>>();
    add_offsets_kernel<<<NBLK_SCAN, SCAN_THREADS>>>();
    place_kernel<<<(N_EDGES / 4 + 255) / 256, 256>>>(eidx);

    if (fork) {
        cudaEventRecord(ev_join, sg);
        cudaStreamWaitEvent(0, ev_join, 0);
    }

    // single-pass fused softmax + gather + ELU + residual (warp per dst)
    aggregate_kernel<<<(N_NODES * 32 + 255) / 256, 256>>>(out);
}

// round 15
// speedup vs baseline: 1.1142x; 1.1142x over previous
#include <cuda_runtime.h>
#include <cuda_bf16.h>
#include <math.h>
#include <stdint.h>

#define N_NODES 100000
#define N_EDGES 1600000
#define DIM 128           // in dim == out dim (8 heads * 16)
#define N_HEADS 8
#define LEAKY 0.2f
#define EPS 1e-16f

#define SA_STRIDE 132
#define SB_STRIDE 133
#define SCAN_THREADS 1024
#define NBLK_SCAN 98      // ceil(100000/1024)

// ---------------- scratch (device globals; no allocation allowed) ----------------
__device__ float g_h[(size_t)N_NODES * DIM];            // x @ W_lin (tf32 mma)
__device__ float g_alpha_l[N_NODES * N_HEADS];
__device__ float g_alpha_r[N_NODES * N_HEADS];
__device__ int   g_deg[N_NODES];
__device__ int   g_row[N_NODES + 1];
__device__ int   g_cursor[N_NODES];
__device__ int   g_csr_src[N_EDGES];
__device__ int   g_partial[NBLK_SCAN];

// ---------------- streams/events: created pre-main (static ctor) ----------------
static cudaStream_t s_side = 0;
static cudaEvent_t  ev_fork = 0, ev_join = 0;
static bool s_ok = false;
namespace {
struct StreamInit {
    StreamInit() {
        s_ok = (cudaStreamCreateWithFlags(&s_side, cudaStreamNonBlocking) == cudaSuccess)
            && (cudaEventCreateWithFlags(&ev_fork, cudaEventDisableTiming) == cudaSuccess)
            && (cudaEventCreateWithFlags(&ev_join, cudaEventDisableTiming) == cudaSuccess);
    }
} s_stream_init;
}

// ============================ CSR build =====================================
__global__ void zero_deg_kernel() {
    int gid = blockIdx.x * blockDim.x + threadIdx.x;
    if (gid < N_NODES) g_deg[gid] = 0;
}

__global__ void hist_kernel(const int* __restrict__ eidx) {
    int gid = blockIdx.x * blockDim.x + threadIdx.x;
    if (gid < N_EDGES / 4) {
        int4 d4 = __ldcs(reinterpret_cast<const int4*>(eidx + N_EDGES) + gid);
        atomicAdd(&g_deg[d4.x], 1);
        atomicAdd(&g_deg[d4.y], 1);
        atomicAdd(&g_deg[d4.z], 1);
        atomicAdd(&g_deg[d4.w], 1);
    }
}

// block-local exclusive scan of g_deg -> g_row (pre-offset), block INCLUSIVE sums -> g_partial
__global__ void scan_local_kernel() {
    __shared__ int warp_sums[32];
    int gid = blockIdx.x * SCAN_THREADS + threadIdx.x;
    int v = (gid < N_NODES) ? g_deg[gid] : 0;
    int x = v;
    int lane = threadIdx.x & 31;
    #pragma unroll
    for (int o = 1; o < 32; o <<= 1) {
        int y = __shfl_up_sync(0xffffffffu, x, o);
        if (lane >= o) x += y;
    }
    if (lane == 31) warp_sums[threadIdx.x >> 5] = x;
    __syncthreads();
    if (threadIdx.x < 32) {
        int w = warp_sums[threadIdx.x];
        #pragma unroll
        for (int o = 1; o < 32; o <<= 1) {
            int y = __shfl_up_sync(0xffffffffu, w, o);
            if (threadIdx.x >= o) w += y;
        }
        warp_sums[threadIdx.x] = w;
    }
    __syncthreads();
    int base = (threadIdx.x >= 32) ? warp_sums[(threadIdx.x >> 5) - 1] : 0;
    int incl = x + base;
    if (gid < N_NODES) g_row[gid] = incl - v;      // exclusive (block-local)
    if (threadIdx.x == SCAN_THREADS - 1) g_partial[blockIdx.x] = incl;
}

// add block offsets; each block computes its own prefix of the 98 partials inline
__global__ void add_offsets_kernel() {
    __shared__ int s_base;
    if (threadIdx.x < 32) {
        int s = 0;
        for (int i = threadIdx.x; i < blockIdx.x && i < NBLK_SCAN; i += 32)
            s += g_partial[i];
        #pragma unroll
        for (int o = 16; o > 0; o >>= 1)
            s += __shfl_xor_sync(0xffffffffu, s, o);
        if (threadIdx.x == 0) s_base = s;
    }
    __syncthreads();
    int gid = blockIdx.x * SCAN_THREADS + threadIdx.x;
    if (gid < N_NODES) {
        int r = g_row[gid] + s_base;
        g_row[gid] = r;
        g_cursor[gid] = r;
    }
    if (gid == 0) g_row[N_NODES] = N_EDGES;
}

__global__ void place_kernel(const int* __restrict__ eidx) {
    int gid = blockIdx.x * blockDim.x + threadIdx.x;
    if (gid < N_EDGES / 4) {
        int4 s4 = __ldcs(reinterpret_cast<const int4*>(eidx) + gid);
        int4 d4 = __ldcs(reinterpret_cast<const int4*>(eidx + N_EDGES) + gid);
        int p0 = atomicAdd(&g_cursor[d4.x], 1);
        int p1 = atomicAdd(&g_cursor[d4.y], 1);
        int p2 = atomicAdd(&g_cursor[d4.z], 1);
        int p3 = atomicAdd(&g_cursor[d4.w], 1);
        g_csr_src[p0] = s4.x;
        g_csr_src[p1] = s4.y;
        g_csr_src[p2] = s4.z;
        g_csr_src[p3] = s4.w;
    }
}

// ================= tf32 tensor-core dual GEMM + fused alpha =================
// One pass over x: computes g_h = x@W_lin (with alpha_l/alpha_r fused from the
// register-resident accumulators) AND d_out = x@W_res.
__device__ __forceinline__ uint32_t f2tf32(float f) {
    uint32_t r;
    asm("cvt.rna.tf32.f32 %0, %1;" : "=r"(r) : "f"(f));
    return r;
}

__global__ void __launch_bounds__(256, 1)
gemm_tf32_kernel(const float* __restrict__ x,
                 const float* __restrict__ Wlin,
                 const float* __restrict__ Wres,
                 const float* __restrict__ att_l,
                 const float* __restrict__ att_r,
                 float* __restrict__ out_res) {
    extern __shared__ uint32_t smem_u[];
    uint32_t* sA = smem_u;                       // [128][SA_STRIDE]
    uint32_t* sB = smem_u + 128 * SA_STRIDE;     // [128][SB_STRIDE] (n,k)
    float* sAl = reinterpret_cast<float*>(sB + 128 * SB_STRIDE);        // [128]
    float* sAr = sAl + DIM;                                             // [128]

    const int tid = threadIdx.x;
    const int row0 = blockIdx.x * 128;

    if (tid < DIM) sAl[tid] = att_l[tid];
    else if (tid < 2 * DIM) sAr[tid - DIM] = att_r[tid - DIM];

    for (int i = tid; i < 128 * 32; i += 256) {
        int r = i >> 5, c4 = i & 31;
        float4 v = make_float4(0.f, 0.f, 0.f, 0.f);
        if (row0 + r < N_NODES)
            v = __ldcs(reinterpret_cast<const float4*>(x + (size_t)(row0 + r) * DIM + c4 * 4));
        uint4 u;
        u.x = f2tf32(v.x); u.y = f2tf32(v.y); u.z = f2tf32(v.z); u.w = f2tf32(v.w);
        *reinterpret_cast<uint4*>(sA + r * SA_STRIDE + c4 * 4) = u;
    }

    const int warp = tid >> 5, lane = tid & 31;
    const int wm = warp >> 1, wn = warp & 1;
    const int g = lane >> 2, tig = lane & 3;

    for (int wsel = 0; wsel < 2; wsel++) {
        const float* W = wsel ? Wres : Wlin;
        for (int i = tid; i < 128 * 128; i += 256) {
            int k = i >> 7, n = i & 127;
            sB[n * SB_STRIDE + k] = f2tf32(W[k * DIM + n]);
        }
        __syncthreads();

        float acc[2][8][4];
        #pragma unroll
        for (int i = 0; i < 2; i++)
            #pragma unroll
            for (int j = 0; j < 8; j++)
                #pragma unroll
                for (int c = 0; c < 4; c++) acc[i][j][c] = 0.f;

        #pragma unroll
        for (int ks = 0; ks < 16; ks++) {
            const int k0 = ks * 8;
            uint32_t bf0[8], bf1[8];
            #pragma unroll
            for (int j = 0; j < 8; j++) {
                int n = wn * 64 + j * 8 + g;
                bf0[j] = sB[n * SB_STRIDE + k0 + tig];
                bf1[j] = sB[n * SB_STRIDE + k0 + 4 + tig];
            }
            #pragma unroll
            for (int i = 0; i < 2; i++) {
                int m = wm * 32 + i * 16;
                uint32_t a0 = sA[(m + g) * SA_STRIDE + k0 + tig];
                uint32_t a1 = sA[(m + 8 + g) * SA_STRIDE + k0 + tig];
                uint32_t a2 = sA[(m + g) * SA_STRIDE + k0 + 4 + tig];
                uint32_t a3 = sA[(m + 8 + g) * SA_STRIDE + k0 + 4 + tig];
                #pragma unroll
                for (int j = 0; j < 8; j++) {
                    asm volatile(
                        "mma.sync.aligned.m16n8k8.row.col.f32.tf32.tf32.f32 "
                        "{%0,%1,%2,%3}, {%4,%5,%6,%7}, {%8,%9}, {%0,%1,%2,%3};"
                        : "+f"(acc[i][j][0]), "+f"(acc[i][j][1]),
                          "+f"(acc[i][j][2]), "+f"(acc[i][j][3])
                        : "r"(a0), "r"(a1), "r"(a2), "r"(a3),
                          "r"(bf0[j]), "r"(bf1[j]));
                }
            }
        }

        #pragma unroll
        for (int i = 0; i < 2; i++) {
            #pragma unroll
            for (int j = 0; j < 8; j++) {
                int col = wn * 64 + j * 8 + tig * 2;
                int r0 = row0 + wm * 32 + i * 16 + g;
                int r1 = r0 + 8;
                if (wsel == 0) {
                    if (r0 < N_NODES)
                        *reinterpret_cast<float2*>(&g_h[(size_t)r0 * DIM + col]) =
                            make_float2(acc[i][j][0], acc[i][j][1]);
                    if (r1 < N_NODES)
                        *reinterpret_cast<float2*>(&g_h[(size_t)r1 * DIM + col]) =
                            make_float2(acc[i][j][2], acc[i][j][3]);
                } else {
                    if (r0 < N_NODES)
                        __stcs(reinterpret_cast<float2*>(out_res + (size_t)r0 * DIM + col),
                               make_float2(acc[i][j][0], acc[i][j][1]));
                    if (r1 < N_NODES)
                        __stcs(reinterpret_cast<float2*>(out_res + (size_t)r1 * DIM + col),
                               make_float2(acc[i][j][2], acc[i][j][3]));
                }
            }
        }

        if (wsel == 0) {
            // ---- fused alpha: logits from register accumulators ----
            // Row r's 64 warp-cols live in the 4 lanes sharing g (tig=0..3).
            // Head h (global) = wn*4 + hl, cols = j in {2*hl, 2*hl+1}.
            #pragma unroll
            for (int i = 0; i < 2; i++) {
                #pragma unroll
                for (int half = 0; half < 2; half++) {
                    #pragma unroll
                    for (int hl = 0; hl < 4; hl++) {
                        const int j0 = hl * 2, j1 = hl * 2 + 1;
                        const int c0 = wn * 64 + j0 * 8 + tig * 2;
                        const int c1 = wn * 64 + j1 * 8 + tig * 2;
                        const int a = half * 2;
                        float pl = acc[i][j0][a]     * sAl[c0]
                                 + acc[i][j0][a + 1] * sAl[c0 + 1]
                                 + acc[i][j1][a]     * sAl[c1]
                                 + acc[i][j1][a + 1] * sAl[c1 + 1];
                        float pr = acc[i][j0][a]     * sAr[c0]
                                 + acc[i][j0][a + 1] * sAr[c0 + 1]
                                 + acc[i][j1][a]     * sAr[c1]
                                 + acc[i][j1][a + 1] * sAr[c1 + 1];
                        pl += __shfl_xor_sync(0xffffffffu, pl, 1);
                        pl += __shfl_xor_sync(0xffffffffu, pl, 2);
                        pr += __shfl_xor_sync(0xffffffffu, pr, 1);
                        pr += __shfl_xor_sync(0xffffffffu, pr, 2);
                        if (tig == 0) {
                            int r = row0 + wm * 32 + i * 16 + half * 8 + g;
                            if (r < N_NODES) {
                                int h = wn * 4 + hl;
                                g_alpha_l[r * N_HEADS + h] = pl;
                                g_alpha_r[r * N_HEADS + h] = pr;
                            }
                        }
                    }
                }
            }
        }
        __syncthreads();
    }
}

// ============ single-pass fused softmax + gather + ELU + residual ===========
// one warp per destination node (exact R9 form, best-known 303.9us).
__global__ void __launch_bounds__(256, 4)
aggregate_kernel(float* __restrict__ out) {
    int wid_g = (blockIdx.x * blockDim.x + threadIdx.x) >> 5;
    int lane = threadIdx.x & 31;
    if (wid_g >= N_NODES) return;
    const int dst = wid_g;
    const int beg = __ldg(&g_row[dst]);
    const int end = __ldg(&g_row[dst + 1]);
    const int head = lane >> 2;                    // head owning this float4

    const float ar = __ldg(&g_alpha_r[dst * N_HEADS + head]);

    float4 acc0 = make_float4(0.f, 0.f, 0.f, 0.f);
    float4 acc1 = make_float4(0.f, 0.f, 0.f, 0.f);
    float hsum = 0.f;                              // identical across 4 lanes of group

    int e = beg;
    for (; e + 3 < end; e += 4) {
        int s0 = __ldg(&g_csr_src[e + 0]);
        int s1 = __ldg(&g_csr_src[e + 1]);
        int s2 = __ldg(&g_csr_src[e + 2]);
        int s3 = __ldg(&g_csr_src[e + 3]);
        float a0 = __ldg(&g_alpha_l[s0 * N_HEADS + head]) + ar;
        float a1 = __ldg(&g_alpha_l[s1 * N_HEADS + head]) + ar;
        float a2 = __ldg(&g_alpha_l[s2 * N_HEADS + head]) + ar;
        float a3 = __ldg(&g_alpha_l[s3 * N_HEADS + head]) + ar;
        a0 = (a0 > 0.f) ? a0 : LEAKY * a0;
        a1 = (a1 > 0.f) ? a1 : LEAKY * a1;
        a2 = (a2 > 0.f) ? a2 : LEAKY * a2;
        a3 = (a3 > 0.f) ? a3 : LEAKY * a3;
        float x0 = __expf(a0), x1 = __expf(a1), x2 = __expf(a2), x3 = __expf(a3);
        float4 h0 = *reinterpret_cast<const float4*>(&g_h[(size_t)s0 * DIM + lane * 4]);
        float4 h1 = *reinterpret_cast<const float4*>(&g_h[(size_t)s1 * DIM + lane * 4]);
        float4 h2 = *reinterpret_cast<const float4*>(&g_h[(size_t)s2 * DIM + lane * 4]);
        float4 h3 = *reinterpret_cast<const float4*>(&g_h[(size_t)s3 * DIM + lane * 4]);
        hsum += (x0 + x1) + (x2 + x3);
        acc0.x = fmaf(h0.x, x0, acc0.x); acc0.y = fmaf(h0.y, x0, acc0.y);
        acc0.z = fmaf(h0.z, x0, acc0.z); acc0.w = fmaf(h0.w, x0, acc0.w);
        acc1.x = fmaf(h1.x, x1, acc1.x); acc1.y = fmaf(h1.y, x1, acc1.y);
        acc1.z = fmaf(h1.z, x1, acc1.z); acc1.w = fmaf(h1.w, x1, acc1.w);
        acc0.x = fmaf(h2.x, x2, acc0.x); acc0.y = fmaf(h2.y, x2, acc0.y);
        acc0.z = fmaf(h2.z, x2, acc0.z); acc0.w = fmaf(h2.w, x2, acc0.w);
        acc1.x = fmaf(h3.x, x3, acc1.x); acc1.y = fmaf(h3.y, x3, acc1.y);
        acc1.z = fmaf(h3.z, x3, acc1.z); acc1.w = fmaf(h3.w, x3, acc1.w);
    }
    for (; e < end; e++) {
        int s = __ldg(&g_csr_src[e]);
        float a = __ldg(&g_alpha_l[s * N_HEADS + head]) + ar;
        a = (a > 0.f) ? a : LEAKY * a;
        float ex = __expf(a);
        float4 hv = *reinterpret_cast<const float4*>(&g_h[(size_t)s * DIM + lane * 4]);
        hsum += ex;
        acc0.x = fmaf(hv.x, ex, acc0.x); acc0.y = fmaf(hv.y, ex, acc0.y);
        acc0.z = fmaf(hv.z, ex, acc0.z); acc0.w = fmaf(hv.w, ex, acc0.w);
    }

    const float inv = 1.f / (hsum + EPS);
    float4 acc;
    acc.x = (acc0.x + acc1.x) * inv;
    acc.y = (acc0.y + acc1.y) * inv;
    acc.z = (acc0.z + acc1.z) * inv;
    acc.w = (acc0.w + acc1.w) * inv;

    float* op = out + (size_t)dst * DIM + lane * 4;
    float4 r = __ldcs(reinterpret_cast<const float4*>(op));  // residual, single use
    float4 o;
    o.x = ((acc.x > 0.f) ? acc.x : expm1f(acc.x)) + r.x;
    o.y = ((acc.y > 0.f) ? acc.y : expm1f(acc.y)) + r.y;
    o.z = ((acc.z > 0.f) ? acc.z : expm1f(acc.z)) + r.z;
    o.w = ((acc.w > 0.f) ? acc.w : expm1f(acc.w)) + r.w;
    __stcs(reinterpret_cast<float4*>(op), o);
}

// ================================ launch ====================================
extern "C" void kernel_launch(void* const* d_in, const int* in_sizes, int n_in,
                              void* d_out, int out_size) {
    const float* x     = (const float*)d_in[0];
    const int*   eidx  = (const int*)d_in[1];
    const float* Wlin  = (const float*)d_in[2];
    const float* att_l = (const float*)d_in[3];
    const float* att_r = (const float*)d_in[4];
    const float* Wres  = (const float*)d_in[5];
    float* out = (float*)d_out;

    static bool attr_set = false;
    const size_t smem_bytes =
        (128 * SA_STRIDE + 128 * SB_STRIDE) * sizeof(uint32_t) + 2 * DIM * sizeof(float);
    if (!attr_set) {
        cudaFuncSetAttribute(gemm_tf32_kernel,
                             cudaFuncAttributeMaxDynamicSharedMemorySize, (int)smem_bytes);
        attr_set = true;
    }

    const bool fork = s_ok;
    cudaStream_t sg = fork ? s_side : (cudaStream_t)0;

    if (fork) {
        cudaEventRecord(ev_fork, 0);
        cudaStreamWaitEvent(sg, ev_fork, 0);
    }

    // Submission order puts gemm 4th (ncu capture slot) without changing the
    // dependency graph: CSR chain on stream 0, GEMM+alpha fused on side stream.
    zero_deg_kernel<<<(N_NODES + 255) / 256, 256>>>();
    hist_kernel<<<(N_EDGES / 4 + 255) / 256, 256>>>(eidx);
    scan_local_kernel<<<NBLK_SCAN, SCAN_THREADS>>>();

    gemm_tf32_kernel<<<(N_NODES + 127) / 128, 256, smem_bytes, sg>>>(
        x, Wlin, Wres, att_l, att_r, out);

    add_offsets_kernel<<<NBLK_SCAN, SCAN_THREADS>>>();
    place_kernel<<<(N_EDGES / 4 + 255) / 256, 256>>>(eidx);

    if (fork) {
        cudaEventRecord(ev_join, sg);
        cudaStreamWaitEvent(0, ev_join, 0);
    }

    // single-pass fused softmax + gather + ELU + residual (warp per dst)
    aggregate_kernel<<<(N_NODES * 32 + 255) / 256, 256>>>(out);
}

// round 16
// speedup vs baseline: 1.2698x; 1.1397x over previous
#include <cuda_runtime.h>
#include <cuda_bf16.h>
#include <math.h>
#include <stdint.h>

#define N_NODES 100000
#define N_EDGES 1600000
#define DIM 128           // in dim == out dim (8 heads * 16)
#define N_HEADS 8
#define LEAKY 0.2f
#define EPS 1e-16f

#define SA_STRIDE 132
#define SB_STRIDE 133
#define SCAN_THREADS 1024
#define NBLK_SCAN 98      // ceil(100000/1024)

// ---------------- scratch (device globals; no allocation allowed) ----------------
__device__ float g_h[(size_t)N_NODES * DIM];            // x @ W_lin (tf32 mma)
__device__ float g_alpha_l[N_NODES * N_HEADS];
__device__ float g_alpha_r[N_NODES * N_HEADS];
__device__ int   g_deg[N_NODES];
__device__ int   g_row[N_NODES + 1];
__device__ int   g_cursor[N_NODES];
__device__ int   g_csr_src[N_EDGES];
__device__ int   g_partial[NBLK_SCAN];

// ---------------- streams/events: created pre-main (static ctor) ----------------
static cudaStream_t s_side = 0;
static cudaEvent_t  ev_fork = 0, ev_join = 0;
static bool s_ok = false;
namespace {
struct StreamInit {
    StreamInit() {
        s_ok = (cudaStreamCreateWithFlags(&s_side, cudaStreamNonBlocking) == cudaSuccess)
            && (cudaEventCreateWithFlags(&ev_fork, cudaEventDisableTiming) == cudaSuccess)
            && (cudaEventCreateWithFlags(&ev_join, cudaEventDisableTiming) == cudaSuccess);
    }
} s_stream_init;
}

// ============================ CSR build =====================================
__global__ void zero_deg_kernel() {
    int gid = blockIdx.x * blockDim.x + threadIdx.x;
    if (gid < N_NODES) g_deg[gid] = 0;
}

__global__ void hist_kernel(const int* __restrict__ eidx) {
    int gid = blockIdx.x * blockDim.x + threadIdx.x;
    if (gid < N_EDGES / 4) {
        int4 d4 = __ldcs(reinterpret_cast<const int4*>(eidx + N_EDGES) + gid);
        atomicAdd(&g_deg[d4.x], 1);
        atomicAdd(&g_deg[d4.y], 1);
        atomicAdd(&g_deg[d4.z], 1);
        atomicAdd(&g_deg[d4.w], 1);
    }
}

// block-local exclusive scan of g_deg -> g_row (pre-offset), block INCLUSIVE sums -> g_partial
__global__ void scan_local_kernel() {
    __shared__ int warp_sums[32];
    int gid = blockIdx.x * SCAN_THREADS + threadIdx.x;
    int v = (gid < N_NODES) ? g_deg[gid] : 0;
    int x = v;
    int lane = threadIdx.x & 31;
    #pragma unroll
    for (int o = 1; o < 32; o <<= 1) {
        int y = __shfl_up_sync(0xffffffffu, x, o);
        if (lane >= o) x += y;
    }
    if (lane == 31) warp_sums[threadIdx.x >> 5] = x;
    __syncthreads();
    if (threadIdx.x < 32) {
        int w = warp_sums[threadIdx.x];
        #pragma unroll
        for (int o = 1; o < 32; o <<= 1) {
            int y = __shfl_up_sync(0xffffffffu, w, o);
            if (threadIdx.x >= o) w += y;
        }
        warp_sums[threadIdx.x] = w;
    }
    __syncthreads();
    int base = (threadIdx.x >= 32) ? warp_sums[(threadIdx.x >> 5) - 1] : 0;
    int incl = x + base;
    if (gid < N_NODES) g_row[gid] = incl - v;      // exclusive (block-local)
    if (threadIdx.x == SCAN_THREADS - 1) g_partial[blockIdx.x] = incl;
}

// add block offsets; each block computes its own prefix of the 98 partials inline
__global__ void add_offsets_kernel() {
    __shared__ int s_base;
    if (threadIdx.x < 32) {
        int s = 0;
        for (int i = threadIdx.x; i < blockIdx.x && i < NBLK_SCAN; i += 32)
            s += g_partial[i];
        #pragma unroll
        for (int o = 16; o > 0; o >>= 1)
            s += __shfl_xor_sync(0xffffffffu, s, o);
        if (threadIdx.x == 0) s_base = s;
    }
    __syncthreads();
    int gid = blockIdx.x * SCAN_THREADS + threadIdx.x;
    if (gid < N_NODES) {
        int r = g_row[gid] + s_base;
        g_row[gid] = r;
        g_cursor[gid] = r;
    }
    if (gid == 0) g_row[N_NODES] = N_EDGES;
}

__global__ void place_kernel(const int* __restrict__ eidx) {
    int gid = blockIdx.x * blockDim.x + threadIdx.x;
    if (gid < N_EDGES / 4) {
        int4 s4 = __ldcs(reinterpret_cast<const int4*>(eidx) + gid);
        int4 d4 = __ldcs(reinterpret_cast<const int4*>(eidx + N_EDGES) + gid);
        int p0 = atomicAdd(&g_cursor[d4.x], 1);
        int p1 = atomicAdd(&g_cursor[d4.y], 1);
        int p2 = atomicAdd(&g_cursor[d4.z], 1);
        int p3 = atomicAdd(&g_cursor[d4.w], 1);
        g_csr_src[p0] = s4.x;
        g_csr_src[p1] = s4.y;
        g_csr_src[p2] = s4.z;
        g_csr_src[p3] = s4.w;
    }
}

// ================= tf32 tensor-core dual GEMM + fused alpha =================
// One pass over x per block (128 rows). Inner loops: 2 weight matrices x 2
// column halves of 64 (sB is 64 cols -> smem ~103KB -> 2 CTAs/SM, 16 warps,
// 2x the latency hiding of the R15 version which ran at occ=12.5%).
__device__ __forceinline__ uint32_t f2tf32(float f) {
    uint32_t r;
    asm("cvt.rna.tf32.f32 %0, %1;" : "=r"(r) : "f"(f));
    return r;
}

__global__ void __launch_bounds__(256, 2)
gemm_tf32_kernel(const float* __restrict__ x,
                 const float* __restrict__ Wlin,
                 const float* __restrict__ Wres,
                 const float* __restrict__ att_l,
                 const float* __restrict__ att_r,
                 float* __restrict__ out_res) {
    extern __shared__ uint32_t smem_u[];
    uint32_t* sA = smem_u;                       // [128][SA_STRIDE]
    uint32_t* sB = smem_u + 128 * SA_STRIDE;     // [64][SB_STRIDE] (n,k) one col half
    float* sAl = reinterpret_cast<float*>(sB + 64 * SB_STRIDE);         // [128]
    float* sAr = sAl + DIM;                                             // [128]

    const int tid = threadIdx.x;
    const int row0 = blockIdx.x * 128;

    if (tid < DIM) sAl[tid] = att_l[tid];
    else if (tid < 2 * DIM) sAr[tid - DIM] = att_r[tid - DIM];

    for (int i = tid; i < 128 * 32; i += 256) {
        int r = i >> 5, c4 = i & 31;
        float4 v = make_float4(0.f, 0.f, 0.f, 0.f);
        if (row0 + r < N_NODES)
            v = __ldcs(reinterpret_cast<const float4*>(x + (size_t)(row0 + r) * DIM + c4 * 4));
        uint4 u;
        u.x = f2tf32(v.x); u.y = f2tf32(v.y); u.z = f2tf32(v.z); u.w = f2tf32(v.w);
        *reinterpret_cast<uint4*>(sA + r * SA_STRIDE + c4 * 4) = u;
    }

    const int warp = tid >> 5, lane = tid & 31;
    const int wm = warp >> 1, wn = warp & 1;     // wm: 4 row groups of 32; wn: col 32-half
    const int g = lane >> 2, tig = lane & 3;

    // 4 passes: wsel (Wlin/Wres) x nh (column half 0/1). Warp covers 32 rows x 32 cols.
    for (int pass = 0; pass < 4; pass++) {
        const int wsel = pass >> 1;
        const int nh = pass & 1;                 // which 64-col half of W
        const float* W = wsel ? Wres : Wlin;

        // load W columns [nh*64, nh*64+64) transposed: sB[n][k], n local 0..63
        for (int i = tid; i < 128 * 64; i += 256) {
            int k = i >> 6, n = i & 63;
            sB[n * SB_STRIDE + k] = f2tf32(W[k * DIM + nh * 64 + n]);
        }
        __syncthreads();

        float acc[2][4][4];                      // 32 rows x 32 cols per warp
        #pragma unroll
        for (int i = 0; i < 2; i++)
            #pragma unroll
            for (int j = 0; j < 4; j++)
                #pragma unroll
                for (int c = 0; c < 4; c++) acc[i][j][c] = 0.f;

        #pragma unroll
        for (int ks = 0; ks < 16; ks++) {
            const int k0 = ks * 8;
            uint32_t bf0[4], bf1[4];
            #pragma unroll
            for (int j = 0; j < 4; j++) {
                int n = wn * 32 + j * 8 + g;     // local n within the 64-col half
                bf0[j] = sB[n * SB_STRIDE + k0 + tig];
                bf1[j] = sB[n * SB_STRIDE + k0 + 4 + tig];
            }
            #pragma unroll
            for (int i = 0; i < 2; i++) {
                int m = wm * 32 + i * 16;
                uint32_t a0 = sA[(m + g) * SA_STRIDE + k0 + tig];
                uint32_t a1 = sA[(m + 8 + g) * SA_STRIDE + k0 + tig];
                uint32_t a2 = sA[(m + g) * SA_STRIDE + k0 + 4 + tig];
                uint32_t a3 = sA[(m + 8 + g) * SA_STRIDE + k0 + 4 + tig];
                #pragma unroll
                for (int j = 0; j < 4; j++) {
                    asm volatile(
                        "mma.sync.aligned.m16n8k8.row.col.f32.tf32.tf32.f32 "
                        "{%0,%1,%2,%3}, {%4,%5,%6,%7}, {%8,%9}, {%0,%1,%2,%3};"
                        : "+f"(acc[i][j][0]), "+f"(acc[i][j][1]),
                          "+f"(acc[i][j][2]), "+f"(acc[i][j][3])
                        : "r"(a0), "r"(a1), "r"(a2), "r"(a3),
                          "r"(bf0[j]), "r"(bf1[j]));
                }
            }
        }

        #pragma unroll
        for (int i = 0; i < 2; i++) {
            #pragma unroll
            for (int j = 0; j < 4; j++) {
                int col = nh * 64 + wn * 32 + j * 8 + tig * 2;   // global column
                int r0 = row0 + wm * 32 + i * 16 + g;
                int r1 = r0 + 8;
                if (wsel == 0) {
                    if (r0 < N_NODES)
                        *reinterpret_cast<float2*>(&g_h[(size_t)r0 * DIM + col]) =
                            make_float2(acc[i][j][0], acc[i][j][1]);
                    if (r1 < N_NODES)
                        *reinterpret_cast<float2*>(&g_h[(size_t)r1 * DIM + col]) =
                            make_float2(acc[i][j][2], acc[i][j][3]);
                } else {
                    if (r0 < N_NODES)
                        __stcs(reinterpret_cast<float2*>(out_res + (size_t)r0 * DIM + col),
                               make_float2(acc[i][j][0], acc[i][j][1]));
                    if (r1 < N_NODES)
                        __stcs(reinterpret_cast<float2*>(out_res + (size_t)r1 * DIM + col),
                               make_float2(acc[i][j][2], acc[i][j][3]));
                }
            }
        }

        if (wsel == 0) {
            // ---- fused alpha for this column half: heads nh*4 .. nh*4+3 ----
            // Warp covers cols [nh*64 + wn*32, +32) = heads nh*4 + wn*2 + {0,1}.
            // Head hl (local 0/1): cols j in {2*hl, 2*hl+1}.
            #pragma unroll
            for (int i = 0; i < 2; i++) {
                #pragma unroll
                for (int half = 0; half < 2; half++) {
                    #pragma unroll
                    for (int hl = 0; hl < 2; hl++) {
                        const int j0 = hl * 2, j1 = hl * 2 + 1;
                        const int c0 = nh * 64 + wn * 32 + j0 * 8 + tig * 2;
                        const int c1 = nh * 64 + wn * 32 + j1 * 8 + tig * 2;
                        const int a = half * 2;
                        float pl = acc[i][j0][a]     * sAl[c0]
                                 + acc[i][j0][a + 1] * sAl[c0 + 1]
                                 + acc[i][j1][a]     * sAl[c1]
                                 + acc[i][j1][a + 1] * sAl[c1 + 1];
                        float pr = acc[i][j0][a]     * sAr[c0]
                                 + acc[i][j0][a + 1] * sAr[c0 + 1]
                                 + acc[i][j1][a]     * sAr[c1]
                                 + acc[i][j1][a + 1] * sAr[c1 + 1];
                        pl += __shfl_xor_sync(0xffffffffu, pl, 1);
                        pl += __shfl_xor_sync(0xffffffffu, pl, 2);
                        pr += __shfl_xor_sync(0xffffffffu, pr, 1);
                        pr += __shfl_xor_sync(0xffffffffu, pr, 2);
                        if (tig == 0) {
                            int r = row0 + wm * 32 + i * 16 + half * 8 + g;
                            if (r < N_NODES) {
                                int h = nh * 4 + wn * 2 + hl;
                                g_alpha_l[r * N_HEADS + h] = pl;
                                g_alpha_r[r * N_HEADS + h] = pr;
                            }
                        }
                    }
                }
            }
        }
        __syncthreads();
    }
}

// ============ single-pass fused softmax + gather + ELU + residual ===========
// one warp per destination node (exact R9 form).
__global__ void __launch_bounds__(256, 4)
aggregate_kernel(float* __restrict__ out) {
    int wid_g = (blockIdx.x * blockDim.x + threadIdx.x) >> 5;
    int lane = threadIdx.x & 31;
    if (wid_g >= N_NODES) return;
    const int dst = wid_g;
    const int beg = __ldg(&g_row[dst]);
    const int end = __ldg(&g_row[dst + 1]);
    const int head = lane >> 2;                    // head owning this float4

    const float ar = __ldg(&g_alpha_r[dst * N_HEADS + head]);

    float4 acc0 = make_float4(0.f, 0.f, 0.f, 0.f);
    float4 acc1 = make_float4(0.f, 0.f, 0.f, 0.f);
    float hsum = 0.f;                              // identical across 4 lanes of group

    int e = beg;
    for (; e + 3 < end; e += 4) {
        int s0 = __ldg(&g_csr_src[e + 0]);
        int s1 = __ldg(&g_csr_src[e + 1]);
        int s2 = __ldg(&g_csr_src[e + 2]);
        int s3 = __ldg(&g_csr_src[e + 3]);
        float a0 = __ldg(&g_alpha_l[s0 * N_HEADS + head]) + ar;
        float a1 = __ldg(&g_alpha_l[s1 * N_HEADS + head]) + ar;
        float a2 = __ldg(&g_alpha_l[s2 * N_HEADS + head]) + ar;
        float a3 = __ldg(&g_alpha_l[s3 * N_HEADS + head]) + ar;
        a0 = (a0 > 0.f) ? a0 : LEAKY * a0;
        a1 = (a1 > 0.f) ? a1 : LEAKY * a1;
        a2 = (a2 > 0.f) ? a2 : LEAKY * a2;
        a3 = (a3 > 0.f) ? a3 : LEAKY * a3;
        float x0 = __expf(a0), x1 = __expf(a1), x2 = __expf(a2), x3 = __expf(a3);
        float4 h0 = *reinterpret_cast<const float4*>(&g_h[(size_t)s0 * DIM + lane * 4]);
        float4 h1 = *reinterpret_cast<const float4*>(&g_h[(size_t)s1 * DIM + lane * 4]);
        float4 h2 = *reinterpret_cast<const float4*>(&g_h[(size_t)s2 * DIM + lane * 4]);
        float4 h3 = *reinterpret_cast<const float4*>(&g_h[(size_t)s3 * DIM + lane * 4]);
        hsum += (x0 + x1) + (x2 + x3);
        acc0.x = fmaf(h0.x, x0, acc0.x); acc0.y = fmaf(h0.y, x0, acc0.y);
        acc0.z = fmaf(h0.z, x0, acc0.z); acc0.w = fmaf(h0.w, x0, acc0.w);
        acc1.x = fmaf(h1.x, x1, acc1.x); acc1.y = fmaf(h1.y, x1, acc1.y);
        acc1.z = fmaf(h1.z, x1, acc1.z); acc1.w = fmaf(h1.w, x1, acc1.w);
        acc0.x = fmaf(h2.x, x2, acc0.x); acc0.y = fmaf(h2.y, x2, acc0.y);
        acc0.z = fmaf(h2.z, x2, acc0.z); acc0.w = fmaf(h2.w, x2, acc0.w);
        acc1.x = fmaf(h3.x, x3, acc1.x); acc1.y = fmaf(h3.y, x3, acc1.y);
        acc1.z = fmaf(h3.z, x3, acc1.z); acc1.w = fmaf(h3.w, x3, acc1.w);
    }
    for (; e < end; e++) {
        int s = __ldg(&g_csr_src[e]);
        float a = __ldg(&g_alpha_l[s * N_HEADS + head]) + ar;
        a = (a > 0.f) ? a : LEAKY * a;
        float ex = __expf(a);
        float4 hv = *reinterpret_cast<const float4*>(&g_h[(size_t)s * DIM + lane * 4]);
        hsum += ex;
        acc0.x = fmaf(hv.x, ex, acc0.x); acc0.y = fmaf(hv.y, ex, acc0.y);
        acc0.z = fmaf(hv.z, ex, acc0.z); acc0.w = fmaf(hv.w, ex, acc0.w);
    }

    const float inv = 1.f / (hsum + EPS);
    float4 acc;
    acc.x = (acc0.x + acc1.x) * inv;
    acc.y = (acc0.y + acc1.y) * inv;
    acc.z = (acc0.z + acc1.z) * inv;
    acc.w = (acc0.w + acc1.w) * inv;

    float* op = out + (size_t)dst * DIM + lane * 4;
    float4 r = __ldcs(reinterpret_cast<const float4*>(op));  // residual, single use
    float4 o;
    o.x = ((acc.x > 0.f) ? acc.x : expm1f(acc.x)) + r.x;
    o.y = ((acc.y > 0.f) ? acc.y : expm1f(acc.y)) + r.y;
    o.z = ((acc.z > 0.f) ? acc.z : expm1f(acc.z)) + r.z;
    o.w = ((acc.w > 0.f) ? acc.w : expm1f(acc.w)) + r.w;
    __stcs(reinterpret_cast<float4*>(op), o);
}

// ================================ launch ====================================
extern "C" void kernel_launch(void* const* d_in, const int* in_sizes, int n_in,
                              void* d_out, int out_size) {
    const float* x     = (const float*)d_in[0];
    const int*   eidx  = (const int*)d_in[1];
    const float* Wlin  = (const float*)d_in[2];
    const float* att_l = (const float*)d_in[3];
    const float* att_r = (const float*)d_in[4];
    const float* Wres  = (const float*)d_in[5];
    float* out = (float*)d_out;

    static bool attr_set = false;
    const size_t smem_bytes =
        (128 * SA_STRIDE + 64 * SB_STRIDE) * sizeof(uint32_t) + 2 * DIM * sizeof(float);
    if (!attr_set) {
        cudaFuncSetAttribute(gemm_tf32_kernel,
                             cudaFuncAttributeMaxDynamicSharedMemorySize, (int)smem_bytes);
        attr_set = true;
    }

    const bool fork = s_ok;
    cudaStream_t sg = fork ? s_side : (cudaStream_t)0;

    if (fork) {
        cudaEventRecord(ev_fork, 0);
        cudaStreamWaitEvent(sg, ev_fork, 0);
    }

    // Submission order keeps gemm 4th (ncu capture slot); dependency graph via streams.
    zero_deg_kernel<<<(N_NODES + 255) / 256, 256>>>();
    hist_kernel<<<(N_EDGES / 4 + 255) / 256, 256>>>(eidx);
    scan_local_kernel<<<NBLK_SCAN, SCAN_THREADS>>>();

    gemm_tf32_kernel<<<(N_NODES + 127) / 128, 256, smem_bytes, sg>>>(
        x, Wlin, Wres, att_l, att_r, out);

    add_offsets_kernel<<<NBLK_SCAN, SCAN_THREADS>>>();
    place_kernel<<<(N_EDGES / 4 + 255) / 256, 256>>>(eidx);

    if (fork) {
        cudaEventRecord(ev_join, sg);
        cudaStreamWaitEvent(0, ev_join, 0);
    }

    // single-pass fused softmax + gather + ELU + residual (warp per dst)
    aggregate_kernel<<<(N_NODES * 32 + 255) / 256, 256>>>(out);
}